// round 9
// baseline (speedup 1.0000x reference)
#include <cuda_runtime.h>
#include <cstdint>

#define BZ     64
#define NC     2048
#define H      14
#define HW     196
#define NCLS   1000
#define SPLITS 16
#define CESPL  8             // CE computed by splits 0..7 only
#define CPB    128           // channels per block
#define TILE_C 16
#define NSTAGE 8             // CPB / TILE_C
#define NBUF   5
#define TPB    256
#define PADW   200
#define NPAIR  105
#define MARGINV 70.0f
#define THRV    125.0f
#define PD_EPS  1e-6f

typedef unsigned long long ull;

// scratch (device globals; no allocations allowed)
__device__ float g_G[BZ * SPLITS * NPAIR];
__device__ float g_cam[BZ * SPLITS * 3 * HW];
__device__ float g_rs[BZ * SPLITS * H];
__device__ float g_cem[BZ * CESPL];
__device__ float g_ces[BZ * CESPL];
__device__ float g_r[BZ];
__device__ int   g_cnt_b[BZ];
__device__ int   g_cnt_all;

// ---------------- f32x2 helpers ----------------
__device__ __forceinline__ ull pk2(float lo, float hi) {
    ull r; asm("mov.b64 %0,{%1,%2};" : "=l"(r) : "f"(lo), "f"(hi)); return r;
}
__device__ __forceinline__ void upk2(float& lo, float& hi, ull v) {
    asm("mov.b64 {%0,%1},%2;" : "=f"(lo), "=f"(hi) : "l"(v));
}
__device__ __forceinline__ ull fma2(ull a, ull b, ull c) {
    ull d; asm("fma.rn.f32x2 %0,%1,%2,%3;" : "=l"(d) : "l"(a), "l"(b), "l"(c)); return d;
}
__device__ __forceinline__ ull add2(ull a, ull b) {
    ull d; asm("add.rn.f32x2 %0,%1,%2;" : "=l"(d) : "l"(a), "l"(b)); return d;
}

// packed-acc offsets: half0 (k even): O0(kk)=7kk-kk(kk-1)/2 ; half1: O1(kk)=6kk-kk(kk-1)/2
__device__ __forceinline__ int O0f(int kk) { return 7 * kk - (kk * (kk - 1)) / 2; }
__device__ __forceinline__ int O1f(int kk) { return 6 * kk - (kk * (kk - 1)) / 2; }

// ---------------------------------------------------------------------------
// cp.async prefetch of one 16-channel tile (16 x 196 floats) into padded smem
// ---------------------------------------------------------------------------
__device__ __forceinline__ void prefetch_tile(const float* __restrict__ src_base,
                                              float* dst, int t) {
#pragma unroll
    for (int it = 0; it < 4; it++) {
        int q = t + it * TPB;            // 784 float4 transfers (16*49)
        if (q < TILE_C * 49) {
            int cc = q / 49;
            int p4 = q - cc * 49;
            const float* src = src_base + cc * HW + p4 * 4;
            unsigned dsts = (unsigned)__cvta_generic_to_shared(dst + cc * PADW + p4 * 4);
            asm volatile("cp.async.cg.shared.global [%0], [%1], 16;\n"
                         :: "r"(dsts), "l"(src));
        }
    }
}

// one column jj of one channel: load 14 strided floats packed, accumulate pairs
template<int HALF>
__device__ __forceinline__ void gram_col(const float* __restrict__ base, int jj,
                                         ull* __restrict__ ap, float* __restrict__ ad) {
    ull c2[7];
#pragma unroll
    for (int m = 0; m < 7; m++) {
        float a = base[(2 * m) * H + jj];
        float b = base[(2 * m + 1) * H + jj];
        c2[m] = pk2(a, b);
    }
    if (HALF == 0) {
#pragma unroll
        for (int kk = 0; kk < 7; kk++) {     // k = 2kk
            float lo, hi; upk2(lo, hi, c2[kk]);
            ull sp = pk2(lo, lo);
#pragma unroll
            for (int m = kk; m < 7; m++)
                ap[O0f(kk) + m - kk] = fma2(sp, c2[m], ap[O0f(kk) + m - kk]);
        }
    } else {
#pragma unroll
        for (int kk = 0; kk < 7; kk++) {     // k = 2kk+1
            float lo, hi; upk2(lo, hi, c2[kk]);
            ad[kk] = fmaf(hi, hi, ad[kk]);   // diagonal (k,k)
            ull sp = pk2(hi, hi);
#pragma unroll
            for (int m = kk + 1; m < 7; m++)
                ap[O1f(kk) + m - kk - 1] = fma2(sp, c2[m], ap[O1f(kk) + m - kk - 1]);
        }
    }
}

// ---------------------------------------------------------------------------
// Fused kernel: fine-grained (1024-block) streaming pass + ticketed finalize
// ---------------------------------------------------------------------------
__global__ void __launch_bounds__(TPB, 2)
k1_fused(const float* __restrict__ feat,
         const float* __restrict__ W,
         const int*   __restrict__ idx,
         const float* __restrict__ pred,
         const int*   __restrict__ cla,
         const float* __restrict__ seg,
         float*       __restrict__ out) {
    extern __shared__ float sh[];
    float* tiles = sh;
    ull*   wpk   = (ull*)(sh + NBUF * TILE_C * PADW);          // {w0,w1}
    ull*   wqk   = wpk + CPB;                                  // {w2,1}
    float* cesh  = sh + NBUF * TILE_C * PADW + 4 * CPB;        // 256 floats

    const int t   = threadIdx.x;
    const int blk = blockIdx.x;
    const int b   = blk >> 4;
    const int s   = blk & 15;
    const int c0  = s * CPB;

    const int half = t >> 7;
    const int r    = t & 127;
    const int cl   = r >> 3;       // channel in tile (0..15)
    const int jg   = r & 7;        // column group

    // weight gather (packed)
    {
        const int i0 = idx[b * 3 + 0];
        const int i1 = idx[b * 3 + 1];
        const int i2 = idx[b * 3 + 2];
        const float* w0 = W + (size_t)i0 * NC;
        const float* w1 = W + (size_t)i1 * NC;
        const float* w2 = W + (size_t)i2 * NC;
        if (t < CPB) {
            int c = c0 + t;
            wpk[t] = pk2(w0[c], w1[c]);
            wqk[t] = pk2(w2[c], 1.0f);
        }
    }

    const float* fbase = feat + ((size_t)b * NC + c0) * HW;

    // prime pipeline (prefetch distance 3, 5 buffers)
    prefetch_tile(fbase,                   tiles,                     t);
    asm volatile("cp.async.commit_group;\n");
    prefetch_tile(fbase +     TILE_C * HW, tiles +     TILE_C * PADW, t);
    asm volatile("cp.async.commit_group;\n");
    prefetch_tile(fbase + 2 * TILE_C * HW, tiles + 2 * TILE_C * PADW, t);
    asm volatile("cp.async.commit_group;\n");

    // ---- CE partial over classes [s*125, s*125+125) for s<8 (overlaps prefetch) ----
    if (s < CESPL) {
        const float* prow = pred + (size_t)b * NCLS + s * 125;
        float x = (t < 125) ? prow[t] : -1e30f;
        float m = x;
#pragma unroll
        for (int off = 16; off >= 1; off >>= 1)
            m = fmaxf(m, __shfl_xor_sync(0xffffffffu, m, off));
        if ((t & 31) == 0) cesh[t >> 5] = m;
        __syncthreads();
        float mx = cesh[0];
#pragma unroll
        for (int w = 1; w < 8; w++) mx = fmaxf(mx, cesh[w]);
        float e = (t < 125) ? expf(x - mx) : 0.0f;
#pragma unroll
        for (int off = 16; off >= 1; off >>= 1)
            e += __shfl_xor_sync(0xffffffffu, e, off);
        __syncthreads();
        if ((t & 31) == 0) cesh[8 + (t >> 5)] = e;
        __syncthreads();
        if (t == 0) {
            float sum = 0.f;
#pragma unroll
            for (int w = 0; w < 8; w++) sum += cesh[8 + w];
            g_cem[b * CESPL + s] = mx;
            g_ces[b * CESPL + s] = sum;
        }
    }

    ull  ap[28];
    float ad[7];
#pragma unroll
    for (int i = 0; i < 28; i++) ap[i] = 0ull;
#pragma unroll
    for (int i = 0; i < 7; i++) ad[i] = 0.f;
    ull cam01 = 0ull, cam2r = 0ull;

    int rdbuf = 0;
#pragma unroll 1
    for (int st = 0; st < NSTAGE; st++) {
        if (st + 3 < NSTAGE) {
            int wb = st + 3;
            int wbuf = wb - (wb / NBUF) * NBUF;
            prefetch_tile(fbase + (size_t)wb * TILE_C * HW,
                          tiles + wbuf * TILE_C * PADW, t);
            asm volatile("cp.async.commit_group;\n");
            asm volatile("cp.async.wait_group 3;\n");
        } else if (st + 2 < NSTAGE) {
            asm volatile("cp.async.wait_group 2;\n");
        } else if (st + 1 < NSTAGE) {
            asm volatile("cp.async.wait_group 1;\n");
        } else {
            asm volatile("cp.async.wait_group 0;\n");
        }
        __syncthreads();

        const float* buf = tiles + rdbuf * TILE_C * PADW;
        rdbuf = (rdbuf + 1 == NBUF) ? 0 : rdbuf + 1;

        // ---- Gram (packed f32x2, half-split over k-parity) ----
        {
            const float* base = buf + cl * PADW;
            if (half == 0) {
                gram_col<0>(base, jg, ap, ad);
                if (jg < 6) gram_col<0>(base, jg + 8, ap, ad);
            } else {
                gram_col<1>(base, jg, ap, ad);
                if (jg < 6) gram_col<1>(base, jg + 8, ap, ad);
            }
        }

        // ---- CAM + rowsum (packed) ----
        if (t < HW) {
            const ull* wp = wpk + st * TILE_C;
            const ull* wq = wqk + st * TILE_C;
#pragma unroll
            for (int cc = 0; cc < TILE_C; cc++) {
                float f = buf[cc * PADW + t];
                ull fs = pk2(f, f);
                cam01 = fma2(fs, wp[cc], cam01);
                cam2r = fma2(fs, wq[cc], cam2r);
            }
        }
    }
    __syncthreads();   // all reads of last tile done before smem repurpose

    // ---- cam + rowsum outputs ----
    if (t < HW) {
        float a, bb, c, rs;
        upk2(a, bb, cam01);
        upk2(c, rs, cam2r);
        float* co = g_cam + (size_t)blk * 3 * HW;
        co[t]          = a;
        co[HW + t]     = bb;
        co[2 * HW + t] = c;
        sh[t] = rs;
    }
    __syncthreads();
    if (t < H) {
        float v = 0.f;
#pragma unroll
        for (int j = 0; j < H; j++) v += sh[t * H + j];
        g_rs[blk * H + t] = v;
    }
    __syncthreads();

    // ---- Gram dump (packed) ----
    ull*   slab0 = (ull*)sh;                   // 128 x 29
    ull*   slab1 = slab0 + 128 * 29;           // 128 x 22
    float* slabd = (float*)(slab1 + 128 * 22); // 128 x 8
    if (half == 0) {
        ull* d = slab0 + (size_t)r * 29;
#pragma unroll
        for (int i = 0; i < 28; i++) d[i] = ap[i];
    } else {
        ull* d = slab1 + (size_t)r * 22;
#pragma unroll
        for (int i = 0; i < 21; i++) d[i] = ap[i];
        float* dd = slabd + (size_t)r * 8;
#pragma unroll
        for (int i = 0; i < 7; i++) dd[i] = ad[i];
    }
    __syncthreads();

    float* gg = g_G + (size_t)blk * NPAIR;
    if (t < 28) {
        int tau = t;
        int kk = 0;
        while (kk < 6 && O0f(kk + 1) <= tau) kk++;
        int m = kk + (tau - O0f(kk));
        int k = 2 * kk, l0 = 2 * m;
        ull S = 0ull;
#pragma unroll 8
        for (int rr = 0; rr < 128; rr++) S = add2(S, slab0[(size_t)rr * 29 + tau]);
        float a, bb; upk2(a, bb, S);
        int qq = k * 14 - (k * (k - 1)) / 2 + (l0 - k);
        gg[qq] = a; gg[qq + 1] = bb;
    } else if (t >= 32 && t < 53) {
        int tau = t - 32;
        int kk = 0;
        while (kk < 6 && O1f(kk + 1) <= tau) kk++;
        int m = kk + 1 + (tau - O1f(kk));
        int k = 2 * kk + 1, l0 = 2 * m;
        ull S = 0ull;
#pragma unroll 8
        for (int rr = 0; rr < 128; rr++) S = add2(S, slab1[(size_t)rr * 22 + tau]);
        float a, bb; upk2(a, bb, S);
        int qq = k * 14 - (k * (k - 1)) / 2 + (l0 - k);
        gg[qq] = a; gg[qq + 1] = bb;
    } else if (t >= 64 && t < 71) {
        int kk = t - 64;
        int k = 2 * kk + 1;
        float v = 0.f;
#pragma unroll 8
        for (int rr = 0; rr < 128; rr++) v += slabd[(size_t)rr * 8 + kk];
        int qq = k * 14 - (k * (k - 1)) / 2;
        gg[qq] = v;
    }
    __syncthreads();

    // ---- ticket: last block of this batch runs finalize ----
    __shared__ int sflag;
    if (t == 0) {
        __threadfence();
        int old = atomicAdd(&g_cnt_b[b], 1);
        sflag = (old == SPLITS - 1);
        if (old == SPLITS - 1) atomicExch(&g_cnt_b[b], 0);   // reset for replay
    }
    __syncthreads();
    if (!sflag) return;
    __threadfence();   // acquire other blocks' g_* writes

    // =================== finalize (per-batch) ===================
    float* camr = sh;               // 3*196
    float* D01s = sh + 588;
    float* D02s = sh + 784;
    float* dstb = sh + 980;
    float* Gs   = sh + 1176;
    float* rss  = sh + 1281;
    float* red  = sh + 1295;
    float* red2 = sh + 1551;
    float* bc   = sh + 1807;        // 8

    if (t < HW) {
#pragma unroll
        for (int j = 0; j < 3; j++) {
            float v = 0.f;
#pragma unroll
            for (int ss = 0; ss < SPLITS; ss++)
                v += g_cam[((size_t)(b * SPLITS + ss) * 3 + j) * HW + t];
            camr[j * HW + t] = v;
        }
    }
    if (t < NPAIR) {
        float v = 0.f;
#pragma unroll
        for (int ss = 0; ss < SPLITS; ss++) v += g_G[(size_t)(b * SPLITS + ss) * NPAIR + t];
        Gs[t] = v;
    }
    if (t < H) {
        float v = 0.f;
#pragma unroll
        for (int ss = 0; ss < SPLITS; ss++) v += g_rs[(b * SPLITS + ss) * H + t];
        rss[t] = v;
    }
    __syncthreads();

    if (t < 32) {
        float mn0 = 1e30f, mn1 = 1e30f, mn2 = 1e30f;
        float mx0 = -1e30f, mx1 = -1e30f, mx2 = -1e30f;
        for (int p = t; p < HW; p += 32) {
            float v0 = camr[p], v1 = camr[HW + p], v2 = camr[2 * HW + p];
            mn0 = fminf(mn0, v0); mx0 = fmaxf(mx0, v0);
            mn1 = fminf(mn1, v1); mx1 = fmaxf(mx1, v1);
            mn2 = fminf(mn2, v2); mx2 = fmaxf(mx2, v2);
        }
#pragma unroll
        for (int off = 16; off >= 1; off >>= 1) {
            mn0 = fminf(mn0, __shfl_xor_sync(0xffffffffu, mn0, off));
            mx0 = fmaxf(mx0, __shfl_xor_sync(0xffffffffu, mx0, off));
            mn1 = fminf(mn1, __shfl_xor_sync(0xffffffffu, mn1, off));
            mx1 = fmaxf(mx1, __shfl_xor_sync(0xffffffffu, mx1, off));
            mn2 = fminf(mn2, __shfl_xor_sync(0xffffffffu, mn2, off));
            mx2 = fmaxf(mx2, __shfl_xor_sync(0xffffffffu, mx2, off));
        }
        if (t == 0) {
            bc[0] = mn0; bc[1] = mn1; bc[2] = mn2;
            bc[3] = 255.f / (mx0 - mn0);
            bc[4] = 255.f / (mx1 - mn1);
            bc[5] = 255.f / (mx2 - mn2);
        }
    }
    __syncthreads();

    if (t < HW) {
        float v0 = (camr[t] - bc[0]) * bc[3];
        float v1 = (camr[HW + t] - bc[1]) * bc[4];
        float v2 = (camr[2 * HW + t] - bc[2]) * bc[5];
        D01s[t] = v0 - v1;
        D02s[t] = v0 - v2;
        dstb[t] = (v0 > THRV) ? 1.f : 0.f;
    }
    __syncthreads();

    float c01 = 0.f, c02 = 0.f;
    if (t < NPAIR) {
        int k = 0, rem = t;
        while (rem >= H - k) { rem -= H - k; k++; }
        int l = k + rem;
        float m01 = 0.f, m02 = 0.f;
#pragma unroll
        for (int i = 0; i < H; i++) {
            m01 = fmaf(D01s[i * H + k], D01s[i * H + l], m01);
            m02 = fmaf(D02s[i * H + k], D02s[i * H + l], m02);
        }
        float wgt = (k == l) ? 1.f : 2.f;
        c01 = wgt * m01 * Gs[t];
        c02 = wgt * m02 * Gs[t];
    }
    red[t]  = c01;
    red2[t] = c02;
    __syncthreads();
    if (t < 32) {
        float s1 = 0.f, s2 = 0.f;
        for (int p = t; p < NPAIR; p += 32) { s1 += red[p]; s2 += red2[p]; }
#pragma unroll
        for (int off = 16; off >= 1; off >>= 1) {
            s1 += __shfl_xor_sync(0xffffffffu, s1, off);
            s2 += __shfl_xor_sync(0xffffffffu, s2, off);
        }
        if (t == 0) { bc[6] = s1; bc[7] = s2; }
    }
    __syncthreads();

    if (t < H) {
        const float* srow = seg + (size_t)b * HW + t * H;
        float a = 0.f;
#pragma unroll
        for (int w = 0; w < H; w++) {
            float d = dstb[t * H + w] - srow[w] + PD_EPS;
            a = fmaf(d, d, a);
        }
        red[t] = sqrtf(a);
    }
    __syncthreads();

    __shared__ int sflag2;
    if (t == 0) {
        float M = -1e30f;
#pragma unroll
        for (int ss = 0; ss < CESPL; ss++) M = fmaxf(M, g_cem[b * CESPL + ss]);
        float S = 0.f;
#pragma unroll
        for (int ss = 0; ss < CESPL; ss++)
            S += g_ces[b * CESPL + ss] * expf(g_cem[b * CESPL + ss] - M);
        float ce = M + logf(S) - pred[(size_t)b * NCLS + cla[b]];

        float ed1 = 0.f;
#pragma unroll
        for (int hh = 0; hh < H; hh++) ed1 += red[hh];
        ed1 *= (1.f / H);

        float e01 = 0.f, e02 = 0.f;
#pragma unroll
        for (int k = 0; k < H; k++) {
            float s01 = 0.f, s02 = 0.f;
#pragma unroll
            for (int i = 0; i < H; i++) {
                s01 += D01s[i * H + k];
                s02 += D02s[i * H + k];
            }
            e01 = fmaf(s01, rss[k], e01);
            e02 = fmaf(s02, rss[k], e02);
        }
        const float epsq = PD_EPS * PD_EPS * (float)(HW * NC);
        float d01 = sqrtf(bc[6] + 2.f * PD_EPS * e01 + epsq) * (1.f / NC);
        float d02 = sqrtf(bc[7] + 2.f * PD_EPS * e02 + epsq) * (1.f / NC);
        g_r[b] = ed1 + fmaxf(MARGINV - d01 - d02, 0.f) + ce;

        __threadfence();
        int o2 = atomicAdd(&g_cnt_all, 1);
        sflag2 = (o2 == BZ - 1);
        if (o2 == BZ - 1) atomicExch(&g_cnt_all, 0);
    }
    __syncthreads();

    if (sflag2 && t == 0) {
        __threadfence();
        float v = 0.f;
#pragma unroll
        for (int i = 0; i < BZ; i++) v += g_r[i];
        out[0] = v * (1.f / BZ);
    }
}

// ---------------------------------------------------------------------------
extern "C" void kernel_launch(void* const* d_in, const int* in_sizes, int n_in,
                              void* d_out, int out_size) {
    const float* pred = (const float*)d_in[0];
    const int*   cla  = (const int*)  d_in[1];
    const float* seg  = (const float*)d_in[2];
    const float* feat = (const float*)d_in[3];
    const float* W    = (const float*)d_in[4];
    const int*   idx  = (const int*)  d_in[5];
    float* out = (float*)d_out;

    // tiles 5*16*200 (16000) + w 512 + ce 256 = 16768 floats = 67072 B
    const int smem = (NBUF * TILE_C * PADW + 4 * CPB + 256) * (int)sizeof(float);
    cudaFuncSetAttribute(k1_fused, cudaFuncAttributeMaxDynamicSharedMemorySize, smem);

    k1_fused<<<BZ * SPLITS, TPB, smem>>>(feat, W, idx, pred, cla, seg, out);
}

// round 10
// speedup vs baseline: 1.1882x; 1.1882x over previous
#include <cuda_runtime.h>
#include <cstdint>

#define BZ     64
#define NC     2048
#define H      14
#define HW     196
#define NCLS   1000
#define SPLITS 4
#define CPB    512
#define TILE_C 16
#define NSTAGE 32            // CPB / TILE_C
#define NBUF   5
#define TPB    256
#define PADW   208           // channel stride (words): even + ==16 mod 32 -> conflict-free LDS.64
#define NPAIR  105
#define MARGINV 70.0f
#define THRV    125.0f
#define PD_EPS  1e-6f

typedef unsigned long long ull;

// scratch (device globals; no allocations allowed)
__device__ float g_G[BZ * SPLITS * NPAIR];
__device__ float g_cam[BZ * SPLITS * 3 * HW];
__device__ float g_rs[BZ * SPLITS * H];
__device__ float g_cem[BZ * SPLITS];
__device__ float g_ces[BZ * SPLITS];
__device__ float g_r[BZ];
__device__ int   g_cnt_b[BZ];
__device__ int   g_cnt_all;

// ---------------- f32x2 helpers ----------------
__device__ __forceinline__ ull pk2(float lo, float hi) {
    ull r; asm("mov.b64 %0,{%1,%2};" : "=l"(r) : "f"(lo), "f"(hi)); return r;
}
__device__ __forceinline__ void upk2(float& lo, float& hi, ull v) {
    asm("mov.b64 {%0,%1},%2;" : "=f"(lo), "=f"(hi) : "l"(v));
}
__device__ __forceinline__ ull fma2(ull a, ull b, ull c) {
    ull d; asm("fma.rn.f32x2 %0,%1,%2,%3;" : "=l"(d) : "l"(a), "l"(b), "l"(c)); return d;
}
__device__ __forceinline__ ull add2(ull a, ull b) {
    ull d; asm("add.rn.f32x2 %0,%1,%2;" : "=l"(d) : "l"(a), "l"(b)); return d;
}

// pair-index helpers (compile-time foldable)
__device__ __forceinline__ constexpr int I0(int a, int b) {
    return a * 7 - (a * (a - 1)) / 2 + (b - a);          // 28 entries, b>=a
}
__device__ __forceinline__ constexpr int I2(int a, int b) {
    return a * 6 - (a * (a - 1)) / 2 + (b - a - 1);      // 21 entries, b>=a+1
}

// ---------------------------------------------------------------------------
// cp.async prefetch of one 16-channel tile into stride-PADW smem
// ---------------------------------------------------------------------------
__device__ __forceinline__ void prefetch_tile(const float* __restrict__ src_base,
                                              float* dst, int t) {
#pragma unroll
    for (int it = 0; it < 4; it++) {
        int q = t + it * TPB;            // 784 float4 transfers (16*49)
        if (q < TILE_C * 49) {
            int cc = q / 49;
            int p4 = q - cc * 49;
            const float* src = src_base + cc * HW + p4 * 4;
            unsigned dsts = (unsigned)__cvta_generic_to_shared(dst + cc * PADW + p4 * 4);
            asm volatile("cp.async.cg.shared.global [%0], [%1], 16;\n"
                         :: "r"(dsts), "l"(src));
        }
    }
}

// ---------------------------------------------------------------------------
// Gram quarter for one channel at column-pair u. p = channel_base + 2u.
// Rows are CONTIGUOUS: row k pair u at word k*14 + 2u -> direct LDS.64, no movs.
// acc lanes = column parity (folded at the end).
//   Q0: (even k, even l)  7 loads, 28 accs
//   Q1: (even k, odd  l) 14 loads, 28 accs
//   Q2: (odd  k, even l) 14 loads, 21 accs
//   Q3: (odd  k, odd  l)  7 loads, 28 accs
// ---------------------------------------------------------------------------
template<int Q>
__device__ __forceinline__ void gram_ch(const float* __restrict__ p,
                                        ull* __restrict__ acc) {
    ull re[7], ro[7];
    if (Q == 0 || Q == 1 || Q == 2) {
#pragma unroll
        for (int a = 0; a < 7; a++) re[a] = *(const ull*)(p + 28 * a);
    }
    if (Q == 1 || Q == 2 || Q == 3) {
#pragma unroll
        for (int a = 0; a < 7; a++) ro[a] = *(const ull*)(p + 28 * a + 14);
    }
    if (Q == 0) {
#pragma unroll
        for (int a = 0; a < 7; a++)
#pragma unroll
            for (int b = a; b < 7; b++)
                acc[I0(a, b)] = fma2(re[a], re[b], acc[I0(a, b)]);
    } else if (Q == 1) {
#pragma unroll
        for (int a = 0; a < 7; a++)
#pragma unroll
            for (int b = a; b < 7; b++)
                acc[I0(a, b)] = fma2(re[a], ro[b], acc[I0(a, b)]);
    } else if (Q == 2) {
#pragma unroll
        for (int a = 0; a < 6; a++)
#pragma unroll
            for (int b = a + 1; b < 7; b++)
                acc[I2(a, b)] = fma2(ro[a], re[b], acc[I2(a, b)]);
    } else {
#pragma unroll
        for (int a = 0; a < 7; a++)
#pragma unroll
            for (int b = a; b < 7; b++)
                acc[I0(a, b)] = fma2(ro[a], ro[b], acc[I0(a, b)]);
    }
}

// ---------------------------------------------------------------------------
// Fused kernel: row-contiguous Gram streaming pass + ticketed finalize
// ---------------------------------------------------------------------------
__global__ void __launch_bounds__(TPB, 2)
k1_fused(const float* __restrict__ feat,
         const float* __restrict__ W,
         const int*   __restrict__ idx,
         const float* __restrict__ pred,
         const int*   __restrict__ cla,
         const float* __restrict__ seg,
         float*       __restrict__ out) {
    extern __shared__ float sh[];
    float* tiles = sh;                                      // 5*16*208 = 16640 floats
    ull*   w0p   = (ull*)(sh + NBUF * TILE_C * PADW);       // 256 ull {w0 even,odd}
    ull*   w1p   = w0p + CPB / 2;
    ull*   w2p   = w1p + CPB / 2;
    float* cesh  = sh + NBUF * TILE_C * PADW + 3 * CPB;     // 256 floats

    const int t   = threadIdx.x;
    const int blk = blockIdx.x;
    const int b   = blk >> 2;
    const int s   = blk & 3;
    const int c0  = s * CPB;

    const int q   = t >> 6;        // pair-parity quarter (2 warps each)
    const int t64 = t & 63;
    const int cl8 = t64 >> 3;      // channel-of-8 (handles cl8 and cl8+8)
    const int u   = t64 & 7;       // column pair (0..6 active)

    // weight gather: packed channel pairs
    {
        const int i0 = idx[b * 3 + 0];
        const int i1 = idx[b * 3 + 1];
        const int i2 = idx[b * 3 + 2];
        const float* w0 = W + (size_t)i0 * NC;
        const float* w1 = W + (size_t)i1 * NC;
        const float* w2 = W + (size_t)i2 * NC;
        int c = c0 + 2 * t;        // t < 256 covers CPB/2 entries
        w0p[t] = pk2(w0[c], w0[c + 1]);
        w1p[t] = pk2(w1[c], w1[c + 1]);
        w2p[t] = pk2(w2[c], w2[c + 1]);
    }

    const float* fbase = feat + ((size_t)b * NC + c0) * HW;

    // prime pipeline (prefetch distance 3, 5 buffers)
    prefetch_tile(fbase,                   tiles,                     t);
    asm volatile("cp.async.commit_group;\n");
    prefetch_tile(fbase +     TILE_C * HW, tiles +     TILE_C * PADW, t);
    asm volatile("cp.async.commit_group;\n");
    prefetch_tile(fbase + 2 * TILE_C * HW, tiles + 2 * TILE_C * PADW, t);
    asm volatile("cp.async.commit_group;\n");

    // ---- CE partial over classes [s*250, s*250+250) (overlaps prefetch) ----
    {
        const float* prow = pred + (size_t)b * NCLS + s * 250;
        float x = (t < 250) ? prow[t] : -1e30f;
        float m = x;
#pragma unroll
        for (int off = 16; off >= 1; off >>= 1)
            m = fmaxf(m, __shfl_xor_sync(0xffffffffu, m, off));
        if ((t & 31) == 0) cesh[t >> 5] = m;
        __syncthreads();
        float mx = cesh[0];
#pragma unroll
        for (int w = 1; w < 8; w++) mx = fmaxf(mx, cesh[w]);
        float e = (t < 250) ? expf(x - mx) : 0.0f;
#pragma unroll
        for (int off = 16; off >= 1; off >>= 1)
            e += __shfl_xor_sync(0xffffffffu, e, off);
        __syncthreads();
        if ((t & 31) == 0) cesh[8 + (t >> 5)] = e;
        __syncthreads();
        if (t == 0) {
            float sum = 0.f;
#pragma unroll
            for (int w = 0; w < 8; w++) sum += cesh[8 + w];
            g_cem[blk] = mx;
            g_ces[blk] = sum;
        }
    }

    ull acc[28];
#pragma unroll
    for (int i = 0; i < 28; i++) acc[i] = 0ull;
    ull cam0a = 0ull, cam1a = 0ull, cam2a = 0ull, rsa = 0ull;
    const ull one2 = pk2(1.0f, 1.0f);

    int rdbuf = 0;
#pragma unroll 1
    for (int st = 0; st < NSTAGE; st++) {
        if (st + 3 < NSTAGE) {
            int wb = st + 3;
            int wbuf = wb - (wb / NBUF) * NBUF;
            prefetch_tile(fbase + (size_t)wb * TILE_C * HW,
                          tiles + wbuf * TILE_C * PADW, t);
            asm volatile("cp.async.commit_group;\n");
            asm volatile("cp.async.wait_group 3;\n");
        } else if (st + 2 < NSTAGE) {
            asm volatile("cp.async.wait_group 2;\n");
        } else if (st + 1 < NSTAGE) {
            asm volatile("cp.async.wait_group 1;\n");
        } else {
            asm volatile("cp.async.wait_group 0;\n");
        }
        __syncthreads();

        const float* buf = tiles + rdbuf * TILE_C * PADW;
        rdbuf = (rdbuf + 1 == NBUF) ? 0 : rdbuf + 1;

        // ---- Gram (row-contiguous LDS.64, zero packing movs) ----
        if (u < 7) {
            const float* p0 = buf + cl8 * PADW + 2 * u;
            const float* p1 = p0 + 8 * PADW;
            if (q == 0)      { gram_ch<0>(p0, acc); gram_ch<0>(p1, acc); }
            else if (q == 1) { gram_ch<1>(p0, acc); gram_ch<1>(p1, acc); }
            else if (q == 2) { gram_ch<2>(p0, acc); gram_ch<2>(p1, acc); }
            else             { gram_ch<3>(p0, acc); gram_ch<3>(p1, acc); }
        }

        // ---- CAM + rowsum: packed channel-pairs ----
        if (t < HW) {
            const ull* wp0 = w0p + st * 8;
            const ull* wp1 = w1p + st * 8;
            const ull* wp2 = w2p + st * 8;
#pragma unroll
            for (int cc = 0; cc < 8; cc++) {
                float f0 = buf[(2 * cc) * PADW + t];
                float f1 = buf[(2 * cc + 1) * PADW + t];
                ull fp = pk2(f0, f1);
                cam0a = fma2(fp, wp0[cc], cam0a);
                cam1a = fma2(fp, wp1[cc], cam1a);
                cam2a = fma2(fp, wp2[cc], cam2a);
                rsa   = fma2(fp, one2,   rsa);
            }
        }
    }
    __syncthreads();   // all reads of last tile done before smem repurpose

    // ---- cam + rowsum outputs (fold channel-parity lanes) ----
    if (t < HW) {
        float a0, b0, a1, b1, a2, b2, ar, br;
        upk2(a0, b0, cam0a);
        upk2(a1, b1, cam1a);
        upk2(a2, b2, cam2a);
        upk2(ar, br, rsa);
        float* co = g_cam + (size_t)blk * 3 * HW;
        co[t]          = a0 + b0;
        co[HW + t]     = a1 + b1;
        co[2 * HW + t] = a2 + b2;
        sh[t] = ar + br;
    }
    __syncthreads();
    if (t < H) {
        float v = 0.f;
#pragma unroll
        for (int j = 0; j < H; j++) v += sh[t * H + j];
        g_rs[blk * H + t] = v;
    }
    __syncthreads();

    // ---- Gram dump: slab[q*64 + t64][28] ull (u=7 rows are zeros) ----
    ull* slab = (ull*)sh;                 // 256 x 28 ull = 57344 B
    {
        ull* d = slab + (size_t)t * 28;
#pragma unroll
        for (int i = 0; i < 28; i++) d[i] = acc[i];
    }
    __syncthreads();

    // ---- reducers: 105 threads fold 64 contributors, then fold lanes ----
    if (t < NPAIR) {
        int k = 0, rem = t;
        while (rem >= H - k) { rem -= H - k; k++; }
        int l = k + rem;
        int qq, ii;
        if (!(k & 1) && !(l & 1))      { qq = 0; ii = I0(k >> 1, l >> 1); }
        else if (!(k & 1))             { qq = 1; ii = I0(k >> 1, (l - 1) >> 1); }
        else if (!(l & 1))             { qq = 2; ii = I2((k - 1) >> 1, l >> 1); }
        else                           { qq = 3; ii = I0((k - 1) >> 1, (l - 1) >> 1); }
        const ull* sp = slab + (size_t)(qq * 64) * 28 + ii;
        ull v = 0ull;
#pragma unroll 8
        for (int rr = 0; rr < 64; rr++) v = add2(v, sp[(size_t)rr * 28]);
        float a, bb; upk2(a, bb, v);
        g_G[(size_t)blk * NPAIR + t] = a + bb;
    }
    __syncthreads();

    // ---- ticket: last block of this batch runs finalize ----
    __shared__ int sflag;
    if (t == 0) {
        __threadfence();
        int old = atomicAdd(&g_cnt_b[b], 1);
        sflag = (old == SPLITS - 1);
        if (old == SPLITS - 1) atomicExch(&g_cnt_b[b], 0);   // reset for replay
    }
    __syncthreads();
    if (!sflag) return;
    __threadfence();   // acquire other blocks' g_* writes

    // =================== finalize (per-batch) ===================
    float* camr = sh;               // 3*196
    float* D01s = sh + 588;
    float* D02s = sh + 784;
    float* dstb = sh + 980;
    float* Gs   = sh + 1176;
    float* rss  = sh + 1281;
    float* red  = sh + 1295;
    float* red2 = sh + 1551;
    float* bc   = sh + 1807;        // 8

    if (t < HW) {
#pragma unroll
        for (int j = 0; j < 3; j++) {
            float v = 0.f;
#pragma unroll
            for (int ss = 0; ss < SPLITS; ss++)
                v += g_cam[((size_t)(b * SPLITS + ss) * 3 + j) * HW + t];
            camr[j * HW + t] = v;
        }
    }
    if (t < NPAIR) {
        float v = 0.f;
#pragma unroll
        for (int ss = 0; ss < SPLITS; ss++) v += g_G[(size_t)(b * SPLITS + ss) * NPAIR + t];
        Gs[t] = v;
    }
    if (t < H) {
        float v = 0.f;
#pragma unroll
        for (int ss = 0; ss < SPLITS; ss++) v += g_rs[(b * SPLITS + ss) * H + t];
        rss[t] = v;
    }
    __syncthreads();

    if (t < 32) {
        float mn0 = 1e30f, mn1 = 1e30f, mn2 = 1e30f;
        float mx0 = -1e30f, mx1 = -1e30f, mx2 = -1e30f;
        for (int p = t; p < HW; p += 32) {
            float v0 = camr[p], v1 = camr[HW + p], v2 = camr[2 * HW + p];
            mn0 = fminf(mn0, v0); mx0 = fmaxf(mx0, v0);
            mn1 = fminf(mn1, v1); mx1 = fmaxf(mx1, v1);
            mn2 = fminf(mn2, v2); mx2 = fmaxf(mx2, v2);
        }
#pragma unroll
        for (int off = 16; off >= 1; off >>= 1) {
            mn0 = fminf(mn0, __shfl_xor_sync(0xffffffffu, mn0, off));
            mx0 = fmaxf(mx0, __shfl_xor_sync(0xffffffffu, mx0, off));
            mn1 = fminf(mn1, __shfl_xor_sync(0xffffffffu, mn1, off));
            mx1 = fmaxf(mx1, __shfl_xor_sync(0xffffffffu, mx1, off));
            mn2 = fminf(mn2, __shfl_xor_sync(0xffffffffu, mn2, off));
            mx2 = fmaxf(mx2, __shfl_xor_sync(0xffffffffu, mx2, off));
        }
        if (t == 0) {
            bc[0] = mn0; bc[1] = mn1; bc[2] = mn2;
            bc[3] = 255.f / (mx0 - mn0);
            bc[4] = 255.f / (mx1 - mn1);
            bc[5] = 255.f / (mx2 - mn2);
        }
    }
    __syncthreads();

    if (t < HW) {
        float v0 = (camr[t] - bc[0]) * bc[3];
        float v1 = (camr[HW + t] - bc[1]) * bc[4];
        float v2 = (camr[2 * HW + t] - bc[2]) * bc[5];
        D01s[t] = v0 - v1;
        D02s[t] = v0 - v2;
        dstb[t] = (v0 > THRV) ? 1.f : 0.f;
    }
    __syncthreads();

    float c01 = 0.f, c02 = 0.f;
    if (t < NPAIR) {
        int k = 0, rem = t;
        while (rem >= H - k) { rem -= H - k; k++; }
        int l = k + rem;
        float m01 = 0.f, m02 = 0.f;
#pragma unroll
        for (int i = 0; i < H; i++) {
            m01 = fmaf(D01s[i * H + k], D01s[i * H + l], m01);
            m02 = fmaf(D02s[i * H + k], D02s[i * H + l], m02);
        }
        float wgt = (k == l) ? 1.f : 2.f;
        c01 = wgt * m01 * Gs[t];
        c02 = wgt * m02 * Gs[t];
    }
    red[t]  = c01;
    red2[t] = c02;
    __syncthreads();
    if (t < 32) {
        float s1 = 0.f, s2 = 0.f;
        for (int p = t; p < NPAIR; p += 32) { s1 += red[p]; s2 += red2[p]; }
#pragma unroll
        for (int off = 16; off >= 1; off >>= 1) {
            s1 += __shfl_xor_sync(0xffffffffu, s1, off);
            s2 += __shfl_xor_sync(0xffffffffu, s2, off);
        }
        if (t == 0) { bc[6] = s1; bc[7] = s2; }
    }
    __syncthreads();

    if (t < H) {
        const float* srow = seg + (size_t)b * HW + t * H;
        float a = 0.f;
#pragma unroll
        for (int w = 0; w < H; w++) {
            float d = dstb[t * H + w] - srow[w] + PD_EPS;
            a = fmaf(d, d, a);
        }
        red[t] = sqrtf(a);
    }
    __syncthreads();

    __shared__ int sflag2;
    if (t == 0) {
        float m0 = g_cem[b * 4 + 0], m1 = g_cem[b * 4 + 1];
        float m2 = g_cem[b * 4 + 2], m3 = g_cem[b * 4 + 3];
        float M = fmaxf(fmaxf(m0, m1), fmaxf(m2, m3));
        float S = g_ces[b * 4 + 0] * expf(m0 - M) + g_ces[b * 4 + 1] * expf(m1 - M)
                + g_ces[b * 4 + 2] * expf(m2 - M) + g_ces[b * 4 + 3] * expf(m3 - M);
        float ce = M + logf(S) - pred[(size_t)b * NCLS + cla[b]];

        float ed1 = 0.f;
#pragma unroll
        for (int hh = 0; hh < H; hh++) ed1 += red[hh];
        ed1 *= (1.f / H);

        float e01 = 0.f, e02 = 0.f;
#pragma unroll
        for (int k = 0; k < H; k++) {
            float s01 = 0.f, s02 = 0.f;
#pragma unroll
            for (int i = 0; i < H; i++) {
                s01 += D01s[i * H + k];
                s02 += D02s[i * H + k];
            }
            e01 = fmaf(s01, rss[k], e01);
            e02 = fmaf(s02, rss[k], e02);
        }
        const float epsq = PD_EPS * PD_EPS * (float)(HW * NC);
        float d01 = sqrtf(bc[6] + 2.f * PD_EPS * e01 + epsq) * (1.f / NC);
        float d02 = sqrtf(bc[7] + 2.f * PD_EPS * e02 + epsq) * (1.f / NC);
        g_r[b] = ed1 + fmaxf(MARGINV - d01 - d02, 0.f) + ce;

        __threadfence();
        int o2 = atomicAdd(&g_cnt_all, 1);
        sflag2 = (o2 == BZ - 1);
        if (o2 == BZ - 1) atomicExch(&g_cnt_all, 0);
    }
    __syncthreads();

    if (sflag2 && t == 0) {
        __threadfence();
        float v = 0.f;
#pragma unroll
        for (int i = 0; i < BZ; i++) v += g_r[i];
        out[0] = v * (1.f / BZ);
    }
}

// ---------------------------------------------------------------------------
extern "C" void kernel_launch(void* const* d_in, const int* in_sizes, int n_in,
                              void* d_out, int out_size) {
    const float* pred = (const float*)d_in[0];
    const int*   cla  = (const int*)  d_in[1];
    const float* seg  = (const float*)d_in[2];
    const float* feat = (const float*)d_in[3];
    const float* W    = (const float*)d_in[4];
    const int*   idx  = (const int*)  d_in[5];
    float* out = (float*)d_out;

    // tiles 5*16*208 (16640) + w 3*512 (1536) + ce 256 = 18432 floats = 73728 B
    const int smem = (NBUF * TILE_C * PADW + 3 * CPB + 256) * (int)sizeof(float);
    cudaFuncSetAttribute(k1_fused, cudaFuncAttributeMaxDynamicSharedMemorySize, smem);

    k1_fused<<<BZ * SPLITS, TPB, smem>>>(feat, W, idx, pred, cla, seg, out);
}